// round 16
// baseline (speedup 1.0000x reference)
#include <cuda_runtime.h>

// CfC recurrent kernel, round 16: 8-CTA clusters, HALF-size footprint per CTA
// so TWO CTAs (different clusters) co-reside per SM and hide each other's
// barrier/latency stalls. B=256, S=2048, C=64, U=128, H=256.
// 32 clusters x 8 CTAs x 256 threads, occupancy 2. CTA rank holds
// W0[:,32r:+32) (24KB) + interleaved head quads for units [16r,+16) (64KB);
// 24/64 GEMM2 k-slices register-pinned. Step structure identical to R11
// (2 cluster barriers/step, DSMEM f/h exchange). Packed fp32x2 FMA.

typedef unsigned long long u64;

#define S_LEN 2048
#define NTHRD 256
#define KREG 24

// SMEM layout (u64 units)
#define OW0   0        // float[192][32]  = 3072 u64 (24KB)
#define OWH   3072     // float[256][64]  = 8192 u64 (64KB)
#define OFEAT 11264    // u64 feat2[192][4]
#define OFSM  12032    // u64 fsm2[256][4]
#define ORED  13056    // u64 red[1024] (red1[8][4][32] / red2[4][4][64] aliased)
#define OTOT  14080
#define SMEM_BYTES (OTOT * 8)   // 112640

__device__ __forceinline__ u64 pack2(float lo, float hi) {
    u64 r;
    asm("mov.b64 %0, {%1, %2};"
        : "=l"(r) : "r"(__float_as_uint(lo)), "r"(__float_as_uint(hi)));
    return r;
}
__device__ __forceinline__ void fma2(u64& d, u64 a, u64 b) {
    asm("fma.rn.f32x2 %0, %1, %2, %0;" : "+l"(d) : "l"(a), "l"(b));
}
__device__ __forceinline__ u64 add2(u64 a, u64 b) {
    u64 r;
    asm("add.rn.f32x2 %0, %1, %2;" : "=l"(r) : "l"(a), "l"(b));
    return r;
}
__device__ __forceinline__ float2 unpk(u64 v) {
    unsigned lo, hi;
    asm("mov.b64 {%0, %1}, %2;" : "=r"(lo), "=r"(hi) : "l"(v));
    return make_float2(__uint_as_float(lo), __uint_as_float(hi));
}
__device__ __forceinline__ unsigned smem_u32(const void* p) {
    unsigned a;
    asm("{ .reg .u64 t; cvta.to.shared.u64 t, %1; cvt.u32.u64 %0, t; }"
        : "=r"(a) : "l"(p));
    return a;
}
__device__ __forceinline__ unsigned mapa_rank(unsigned addr, unsigned rank) {
    unsigned r;
    asm("mapa.shared::cluster.u32 %0, %1, %2;" : "=r"(r) : "r"(addr), "r"(rank));
    return r;
}
__device__ __forceinline__ void st_cluster(unsigned addr, u64 v) {
    asm volatile("st.shared::cluster.b64 [%0], %1;" :: "r"(addr), "l"(v) : "memory");
}
__device__ __forceinline__ unsigned ctarank() {
    unsigned r;
    asm("mov.u32 %0, %%cluster_ctarank;" : "=r"(r));
    return r;
}
#define CLUSTER_BAR() do { \
    asm volatile("barrier.cluster.arrive.aligned;" ::: "memory"); \
    asm volatile("barrier.cluster.wait.aligned;"   ::: "memory"); \
} while (0)

__global__ void __launch_bounds__(NTHRD, 2) __cluster_dims__(8, 1, 1)
cfc_kernel(
    const float* __restrict__ x_codes, const float* __restrict__ h0,
    const float* __restrict__ tsp,
    const float* __restrict__ W0, const float* __restrict__ b0,
    const float* __restrict__ W1, const float* __restrict__ b1,
    const float* __restrict__ W2, const float* __restrict__ b2,
    const float* __restrict__ Wa, const float* __restrict__ ba,
    const float* __restrict__ Wb, const float* __restrict__ bb,
    float* __restrict__ out)
{
    extern __shared__ u64 smu[];
    float* sW0 = (float*)(smu + OW0);
    float* sWH = (float*)(smu + OWH);
    u64* feat2 = smu + OFEAT;
    u64* fsm2  = smu + OFSM;
    u64* red   = smu + ORED;

    const int tid = threadIdx.x;
    const unsigned rank = ctarank();            // 0..7
    const int brow = (blockIdx.x >> 3) * 8;     // cluster owns 8 rows

    // ---- one-time: W0 slice [192][32] (cols 32*rank..) ----
    for (int idx = tid; idx < 192 * 8; idx += NTHRD) {      // float4 units
        int k = idx >> 3, q = idx & 7;
        ((float4*)sW0)[idx] =
            *(const float4*)(W0 + (size_t)k * 256 + rank * 32 + q * 4);
    }
    // ---- head slice interleaved: sWH[k][4j+h] = Wh[k][16*rank+j] ----
    for (int idx = tid; idx < 256 * 64; idx += NTHRD) {
        int k = idx >> 6, c = idx & 63, j = c >> 2, h = c & 3;
        const float* src = (h == 0 ? W1 : h == 1 ? W2 : h == 2 ? Wa : Wb);
        sWH[idx] = src[(size_t)k * 128 + 16 * rank + j];
    }
    // ---- h0 into feat2[64+u][rp] ----
    for (int idx = tid; idx < 512; idx += NTHRD) {
        int u = idx & 127, rp = idx >> 7;
        feat2[(64 + u) * 4 + rp] = pack2(h0[(size_t)(brow + 2 * rp) * 128 + u],
                                         h0[(size_t)(brow + 2 * rp + 1) * 128 + u]);
    }

    // ---- role constants ----
    // GEMM1: 16 col-groups(2) x 8 kg(24) x 2 row-pair halves
    const int cg1  = tid & 15;
    const int kg1  = (tid >> 4) & 7;
    const int rph1 = (tid >> 7) & 1;
    const int k1b  = kg1 * 24;
    // reduce1 (tid<128): 32 cols x 4 rps
    const int col1 = tid & 31;
    const int rp1  = tid >> 5;                  // valid for tid<128
    const int gc1  = 32 * (int)rank + col1;
    const u64 b0d  = pack2(b0[gc1], b0[gc1]);
    // GEMM2: 32 col-groups(2 of 64 local) x 4 kg(64) x 2 rp halves
    const int cg2  = tid & 31;
    const int kg2  = (tid >> 5) & 3;
    const int rph2 = (tid >> 7) & 1;
    const float* wp2c = sWH + (kg2 * 64) * 64 + 2 * cg2;
    const u64* fp2c   = fsm2 + (kg2 * 64) * 4 + rph2 * 2;
    // gate (tid<64): 16 units x 4 rps
    const int jg  = tid & 15;
    const int rpg = (tid >> 4) & 3;
    const int ug  = 16 * (int)rank + jg;
    const u64 b1d = pack2(b1[ug], b1[ug]);
    const u64 b2d = pack2(b2[ug], b2[ug]);
    const u64 bad = pack2(ba[ug], ba[ug]);
    const u64 bbd = pack2(bb[ug], bb[ug]);
    const int gr0 = brow + 2 * rpg;
    const float* tsa = tsp + (size_t)gr0 * S_LEN;
    const float* tsb = tsp + (size_t)(gr0 + 1) * S_LEN;
    float* outa = out + (size_t)gr0 * S_LEN * 128 + ug;
    float* outb = out + (size_t)(gr0 + 1) * S_LEN * 128 + ug;
    // x writers (tid>=128): 64 ch x 2 rp-pairs; each thread owns 2 feat slots
    const int xt   = tid & 127;
    const int ch   = xt & 63;
    const int rpx2 = (xt >> 6) & 1;             // rp pair: {2*rpx2, 2*rpx2+1}
    const int xr0w = brow + 4 * rpx2;           // rows xr0w..xr0w+3
    const float* xp0 = x_codes + (size_t)(xr0w + 0) * S_LEN * 64 + ch;
    const float* xp1 = x_codes + (size_t)(xr0w + 1) * S_LEN * 64 + ch;
    const float* xp2 = x_codes + (size_t)(xr0w + 2) * S_LEN * 64 + ch;
    const float* xp3 = x_codes + (size_t)(xr0w + 3) * S_LEN * 64 + ch;

    // x(0) write + x(1) prefetch
    float xr0 = 0.f, xr1 = 0.f, xr2 = 0.f, xr3 = 0.f;
    if (tid >= 128) {
        feat2[ch * 4 + 2 * rpx2] =
            pack2((xp0[0] - 65.0f) * 0.01f, (xp1[0] - 65.0f) * 0.01f);
        feat2[ch * 4 + 2 * rpx2 + 1] =
            pack2((xp2[0] - 65.0f) * 0.01f, (xp3[0] - 65.0f) * 0.01f);
        xr0 = xp0[64]; xr1 = xp1[64]; xr2 = xp2[64]; xr3 = xp3[64];
    }
    __syncthreads();
    CLUSTER_BAR();   // weights, h0, x(0) visible cluster-wide

    // ---- remote base addresses ----
    unsigned fsmb[8], featb[8];
    {
        unsigned lf = smem_u32(fsm2), lh = smem_u32(feat2);
        #pragma unroll
        for (int r = 0; r < 8; ++r) {
            fsmb[r]  = mapa_rank(lf, (unsigned)r);
            featb[r] = mapa_rank(lh, (unsigned)r);
        }
    }

    // ---- pin first KREG GEMM2 weight k-slices in registers ----
    float2 wreg[KREG];
    #pragma unroll
    for (int k = 0; k < KREG; ++k) wreg[k] = *(const float2*)(wp2c + k * 64);

    for (int s = 0; s < S_LEN; ++s) {
        float tsv0 = 0.f, tsv1 = 0.f;
        if (tid < 64) { tsv0 = tsa[s]; tsv1 = tsb[s]; }
        __syncthreads();  // S1: feat ready (h via prev BAR_B, x via prev reduce slot)

        // ---- GEMM1: 2 cols x 2 rps over 24 k ----
        u64 a00 = 0, a01 = 0, a10 = 0, a11 = 0;
        {
            const float* wp = sW0 + k1b * 32 + 2 * cg1;
            const u64* fp = feat2 + k1b * 4 + rph1 * 2;
            #pragma unroll 12
            for (int k = 0; k < 24; ++k) {
                float2 w = *(const float2*)(wp + k * 32);
                u64 w0 = pack2(w.x, w.x), w1 = pack2(w.y, w.y);
                ulonglong2 f = *(const ulonglong2*)(fp + k * 4);
                fma2(a00, f.x, w0); fma2(a01, f.y, w0);
                fma2(a10, f.x, w1); fma2(a11, f.y, w1);
            }
        }
        {   // red1 [kg8][rp4][col32]
            u64* rb = red + kg1 * 128 + (rph1 * 2) * 32 + 2 * cg1;
            *(ulonglong2*)(rb)      = make_ulonglong2(a00, a10);
            *(ulonglong2*)(rb + 32) = make_ulonglong2(a01, a11);
        }
        __syncthreads();  // S2: red1 ready; GEMM1 feat reads complete

        if (tid < 128) {
            // ---- reduce1 (8 partials) + lecun_tanh + push f to 8 CTAs ----
            const u64* rr = red + rp1 * 32 + col1;
            u64 ss = rr[0];
            #pragma unroll
            for (int q = 1; q < 8; ++q) ss = add2(ss, rr[q * 128]);
            ss = add2(ss, b0d);
            float2 v = unpk(ss);
            u64 fv = pack2(1.7159f * tanhf(0.666f * v.x),
                           1.7159f * tanhf(0.666f * v.y));
            unsigned off = (unsigned)((gc1 * 4 + rp1) * 8);
            #pragma unroll
            for (int r = 0; r < 8; ++r) st_cluster(fsmb[r] + off, fv);
        } else if (s + 1 < S_LEN) {
            // ---- write x(s+1) (GEMM1 reads done at S2), prefetch x(s+2) ----
            feat2[ch * 4 + 2 * rpx2] =
                pack2((xr0 - 65.0f) * 0.01f, (xr1 - 65.0f) * 0.01f);
            feat2[ch * 4 + 2 * rpx2 + 1] =
                pack2((xr2 - 65.0f) * 0.01f, (xr3 - 65.0f) * 0.01f);
            if (s + 2 < S_LEN) {
                size_t o = (size_t)(s + 2) * 64;
                xr0 = xp0[o]; xr1 = xp1[o]; xr2 = xp2[o]; xr3 = xp3[o];
            }
        }
        CLUSTER_BAR();  // BAR_A: fsm complete everywhere

        // ---- GEMM2: 2 cols x 2 rps over 64 k (24 reg + 40 smem weights) ----
        u64 q00 = 0, q01 = 0, q10 = 0, q11 = 0;
        #pragma unroll
        for (int k = 0; k < KREG; ++k) {
            float2 w = wreg[k];
            u64 w0 = pack2(w.x, w.x), w1 = pack2(w.y, w.y);
            ulonglong2 f = *(const ulonglong2*)(fp2c + k * 4);
            fma2(q00, f.x, w0); fma2(q01, f.y, w0);
            fma2(q10, f.x, w1); fma2(q11, f.y, w1);
        }
        #pragma unroll 10
        for (int k = KREG; k < 64; ++k) {
            float2 w = *(const float2*)(wp2c + k * 64);
            u64 w0 = pack2(w.x, w.x), w1 = pack2(w.y, w.y);
            ulonglong2 f = *(const ulonglong2*)(fp2c + k * 4);
            fma2(q00, f.x, w0); fma2(q01, f.y, w0);
            fma2(q10, f.x, w1); fma2(q11, f.y, w1);
        }
        {   // red2 [kg4][rp4][col64] (aliases red1 — BAR_A ordered)
            u64* rb = red + kg2 * 256 + (rph2 * 2) * 64 + 2 * cg2;
            *(ulonglong2*)(rb)      = make_ulonglong2(q00, q10);
            *(ulonglong2*)(rb + 64) = make_ulonglong2(q01, q11);
        }
        __syncthreads();  // S3: red2 ready

        // ---- gate: reduce 4 kg, sigmoid blend, out + h-push to 8 CTAs ----
        if (tid < 64) {
            const u64* rr = red + rpg * 64 + 4 * jg;
            ulonglong2 g0 = *(const ulonglong2*)(rr);       // (ff1,ff2) partial
            ulonglong2 g1 = *(const ulonglong2*)(rr + 2);   // (ta, tb ) partial
            u64 p1 = g0.x, p2 = g0.y, pa = g1.x, pb = g1.y;
            #pragma unroll
            for (int q = 1; q < 4; ++q) {
                ulonglong2 u0 = *(const ulonglong2*)(rr + q * 256);
                ulonglong2 u1 = *(const ulonglong2*)(rr + q * 256 + 2);
                p1 = add2(p1, u0.x); p2 = add2(p2, u0.y);
                pa = add2(pa, u1.x); pb = add2(pb, u1.y);
            }
            p1 = add2(p1, b1d); p2 = add2(p2, b2d);
            pa = add2(pa, bad); pb = add2(pb, bbd);
            float2 f1 = unpk(p1), f2 = unpk(p2), av = unpk(pa), bv = unpk(pb);
            float ti0 = 1.0f / (1.0f + expf(av.x * tsv0 - bv.x));
            float ti1 = 1.0f / (1.0f + expf(av.y * tsv1 - bv.y));
            float nh0 = f1.x + ti0 * (f2.x - f1.x);
            float nh1 = f1.y + ti1 * (f2.y - f1.y);
            outa[(size_t)s * 128] = nh0;
            outb[(size_t)s * 128] = nh1;
            u64 hv = pack2(nh0, nh1);
            unsigned off = (unsigned)(((64 + ug) * 4 + rpg) * 8);
            #pragma unroll
            for (int r = 0; r < 8; ++r) st_cluster(featb[r] + off, hv);
        }
        CLUSTER_BAR();  // BAR_B: h delivered everywhere; exit-safe on last step
    }
}

extern "C" void kernel_launch(void* const* d_in, const int* in_sizes, int n_in,
                              void* d_out, int out_size) {
    const float* x_codes = (const float*)d_in[0];
    const float* h0      = (const float*)d_in[1];
    const float* tsp     = (const float*)d_in[2];
    const float* W0      = (const float*)d_in[3];
    const float* b0      = (const float*)d_in[4];
    const float* W1      = (const float*)d_in[5];
    const float* b1      = (const float*)d_in[6];
    const float* W2      = (const float*)d_in[7];
    const float* b2      = (const float*)d_in[8];
    const float* Wa      = (const float*)d_in[9];
    const float* ba      = (const float*)d_in[10];
    const float* Wb      = (const float*)d_in[11];
    const float* bb      = (const float*)d_in[12];
    float* out = (float*)d_out;

    cudaFuncSetAttribute(cfc_kernel,
                         cudaFuncAttributeMaxDynamicSharedMemorySize, SMEM_BYTES);

    cfc_kernel<<<256, NTHRD, SMEM_BYTES>>>(
        x_codes, h0, tsp, W0, b0, W1, b1, W2, b2, Wa, ba, Wb, bb, out);
}